// round 15
// baseline (speedup 1.0000x reference)
#include <cuda_runtime.h>
#include <cuda_fp16.h>
#include <cstdint>
#include <math.h>

#define M_TOTAL 32768
#define SEQ     8192
#define H       1024
#define NB      4
#define KBA     2048                 // bytes per A row (1024 fp16)
#define KBB     2048                 // bytes per B row (1024 fp16)
#define NCH     16                   // 16 K-chunks of 64 fp16 (128B)
#define STAGE_BYTES 32768            // 16KB A + 16KB B
#define SMEM_TOTAL (3*STAGE_BYTES)   // 96KB

// ---------------- scratch -----------------------------------------------
__device__ __half g_Ax[(size_t)M_TOTAL * H];     // x, fp16
__device__ __half g_Vp[(size_t)M_TOTAL * H];     // V', fp16
__device__ __half g_Qf[(size_t)M_TOTAL * H];     // elu(q)+1, fp16
__device__ __half g_Bqkv[(size_t)3072 * H];      // [Q rows | K/V interleaved rows]
__device__ __half g_Bo [(size_t)1024 * H];       // out weights
__device__ float  g_KV[NB * H];
__device__ float  g_Ksum[NB * H];

// ---------------- helpers ------------------------------------------------
__device__ __forceinline__ uint32_t smem_u32(const void* p) {
    uint32_t a;
    asm("{ .reg .u64 t; cvta.to.shared.u64 t, %1; cvt.u32.u64 %0, t; }" : "=r"(a) : "l"(p));
    return a;
}
__device__ __forceinline__ void cp16(uint32_t dst, const void* src) {
    asm volatile("cp.async.cg.shared.global [%0], [%1], 16;" :: "r"(dst), "l"(src));
}
__device__ __forceinline__ void cpcommit() {
    asm volatile("cp.async.commit_group;" ::: "memory");
}
template <int N> __device__ __forceinline__ void cpwait() {
    asm volatile("cp.async.wait_group %0;" :: "n"(N) : "memory");
}
__device__ __forceinline__ void ldmx4(uint32_t* r, uint32_t addr) {
    asm volatile("ldmatrix.sync.aligned.m8n8.x4.shared.b16 {%0,%1,%2,%3}, [%4];"
                 : "=r"(r[0]), "=r"(r[1]), "=r"(r[2]), "=r"(r[3]) : "r"(addr));
}
__device__ __forceinline__ void mma16816(float* d, const uint32_t* a, uint32_t b0, uint32_t b1) {
    asm volatile(
        "mma.sync.aligned.m16n8k16.row.col.f32.f16.f16.f32 "
        "{%0,%1,%2,%3}, {%4,%5,%6,%7}, {%8,%9}, {%0,%1,%2,%3};"
        : "+f"(d[0]), "+f"(d[1]), "+f"(d[2]), "+f"(d[3])
        : "r"(a[0]), "r"(a[1]), "r"(a[2]), "r"(a[3]), "r"(b0), "r"(b1));
}
__device__ __forceinline__ float elu1(float x) { return x > 0.f ? x + 1.f : __expf(x); }
__device__ __forceinline__ float fast_tanh(float x) {
    float y;
    asm("tanh.approx.f32 %0, %1;" : "=f"(y) : "f"(x));
    return y;
}
__device__ __forceinline__ float gelu(float v) {
    float t = 0.7978845608028654f * (v + 0.044715f * v * v * v);
    return 0.5f * v * (1.0f + fast_tanh(t));
}

// ---------------- small kernels ------------------------------------------
// x fp32 -> fp16, 8 elems/thread (+ first 16 blocks zero reduction buffers)
__global__ __launch_bounds__(256) void conv_x_kernel(const float* __restrict__ x) {
    if (blockIdx.x < 16) {
        int i = blockIdx.x * 256 + threadIdx.x;
        g_KV[i] = 0.f;
        g_Ksum[i] = 0.f;
    }
    size_t idx = (size_t)blockIdx.x * 256 + threadIdx.x;
    size_t e = idx << 3;
    float4 a = *(const float4*)&x[e];
    float4 b = *(const float4*)&x[e + 4];
    __half2 o[4];
    o[0] = {__float2half(a.x), __float2half(a.y)};
    o[1] = {__float2half(a.z), __float2half(a.w)};
    o[2] = {__float2half(b.x), __float2half(b.y)};
    o[3] = {__float2half(b.z), __float2half(b.w)};
    *(uint4*)&g_Ax[e] = *(uint4*)o;
}

// weights -> fp16 rows via tiled 64x64 smem transpose.
// B layout: rows 0-1023 = Q; rows 1024-3071 = K/V interleaved 64-blocks
// [32 K-ch | 32 matching V-ch]. Separate g_Bo for output weights.
__global__ __launch_bounds__(256) void conv_w_kernel(
    const float* __restrict__ wq, const float* __restrict__ wk,
    const float* __restrict__ wv, const float* __restrict__ wo) {
    __shared__ float s[64][65];
    const int tid = threadIdx.x;
    const int which = blockIdx.y;
    const int k0 = (blockIdx.x >> 4) * 64;
    const int h0 = (blockIdx.x & 15) * 64;
    const float* w = (which == 0) ? wq : (which == 1) ? wk : (which == 2) ? wv : wo;

    #pragma unroll
    for (int pass = 0; pass < 4; pass++) {
        int r = (tid >> 4) + pass * 16;
        int c4 = (tid & 15) << 2;
        float4 v = *(const float4*)&w[(size_t)(k0 + r) * H + h0 + c4];
        s[r][c4 + 0] = v.x; s[r][c4 + 1] = v.y;
        s[r][c4 + 2] = v.z; s[r][c4 + 3] = v.w;
    }
    __syncthreads();

    #pragma unroll
    for (int pass = 0; pass < 2; pass++) {
        int idx = pass * 256 + tid;
        int hh = idx >> 3;
        int seg = idx & 7;
        int h = h0 + hh;
        __half* row;
        if (which == 0)      row = &g_Bqkv[(size_t)h * H];
        else if (which == 1) row = &g_Bqkv[(size_t)(1024 + (h >> 5) * 64 + (h & 31)) * H];
        else if (which == 2) row = &g_Bqkv[(size_t)(1024 + (h >> 5) * 64 + 32 + (h & 31)) * H];
        else                 row = &g_Bo[(size_t)h * H];
        int kk = seg * 8;
        __half2 h4[4];
        #pragma unroll
        for (int i = 0; i < 4; i++)
            h4[i] = {__float2half(s[kk + 2 * i][hh]), __float2half(s[kk + 2 * i + 1][hh])};
        *(uint4*)&row[k0 + kk] = *(uint4*)h4;
    }
}

// V' = Qf*KV / (Qf*Ksum + 1e-6) -> fp16.
// Latency-optimized: 8 rows/block (grid 4096), 4 independent iters/thread,
// streaming hints (ldcs/stcs); KV/Ksum via __ldg (L1-resident, 8KB/batch).
__global__ __launch_bounds__(256) void vprime_kernel() {
    const int tid = threadIdx.x;
    const int m0 = blockIdx.x * 8;
    const int bn = m0 >> 13;                 // m0 / SEQ
    const float* kvb = &g_KV[bn * H];
    const float* ksb = &g_Ksum[bn * H];
    const size_t base = (size_t)m0 * H;

    #pragma unroll
    for (int it = 0; it < 4; it++) {
        size_t e = base + (size_t)it * 2048 + (size_t)tid * 8;
        int h = (int)(e & 1023);
        uint4 qr = __ldcs((const uint4*)&g_Qf[e]);
        const __half* qh = (const __half*)&qr;
        __half o[8];
        #pragma unroll
        for (int i = 0; i < 8; i++) {
            float q  = __half2float(qh[i]);
            float kv = __ldg(&kvb[h + i]);
            float ks = __ldg(&ksb[h + i]);
            o[i] = __float2half(__fdividef(q * kv, fmaf(q, ks, 1e-6f)));
        }
        __stcs((uint4*)&g_Vp[e], *(uint4*)o);
    }
}

// ---------------- HMMA GEMM ----------------------------------------------
// CTA tile 128x128, 128 threads (4 warps), warp tile 64x64, 3-stage pipe,
// 2 CTA/SM. Producer cp.async issues spread across the 4 ks iterations.
// MODE 0: fused QKV-GEMM (N=3072). n0<1024: Q tile -> elu1 -> g_Qf.
//         n0>=1024: KV tile -> per-channel reduction.
// MODE 1: out-GEMM (N=1024) -> bias+gelu -> out.
template <int MODE>
__global__ __launch_bounds__(128, 2) void gemm_kernel(
    const float* __restrict__ b0p,
    const float* __restrict__ b1p,
    const float* __restrict__ b2p,
    float* __restrict__ outp)
{
    extern __shared__ __align__(1024) char smv[];
    const uint32_t sb = smem_u32(smv);
    const int tid = threadIdx.x;
    const int w = tid >> 5, l = tid & 31;

    const size_t m0 = (size_t)blockIdx.y * 128;
    const int n0 = blockIdx.x * 128;

    const __half* A = (MODE == 1) ? g_Vp : g_Ax;
    const __half* B = (MODE == 1) ? g_Bo : g_Bqkv;

    // cp.async: 128 threads cover 128 rows x 128B for A and B each
    const char* Asrc = (const char*)A + (m0 + (tid >> 3)) * (size_t)KBA + ((tid & 7) << 4);
    const char* Bsrc = (const char*)B + ((size_t)(n0 + (tid >> 3))) * KBB + ((tid & 7) << 4);
    const uint32_t dst0 = ((tid >> 3) << 7) + ((((tid & 7) << 4)) ^ ((((tid >> 3) & 7)) << 4));

    auto load_chunk = [&](int ch, int s) {
        uint32_t sa = sb + s * STAGE_BYTES + dst0;
        uint32_t sbm = sa + 16384;
        const char* as = Asrc + (size_t)ch * 128;
        const char* bs = Bsrc + (size_t)ch * 128;
        #pragma unroll
        for (int j = 0; j < 8; j++) cp16(sa + (j << 11), as + j * (size_t)(16 * KBA));
        #pragma unroll
        for (int j = 0; j < 8; j++) cp16(sbm + (j << 11), bs + j * (size_t)(16 * KBB));
        cpcommit();
    };

    // quarter of a chunk load (2 A row-groups + 2 B row-groups per thread)
    auto load_quarter = [&](int ch, int s, int q) {
        uint32_t sa = sb + s * STAGE_BYTES + dst0;
        uint32_t sbm = sa + 16384;
        const char* as = Asrc + (size_t)ch * 128;
        const char* bs = Bsrc + (size_t)ch * 128;
        #pragma unroll
        for (int j = 2 * q; j < 2 * q + 2; j++) {
            cp16(sa + (j << 11), as + j * (size_t)(16 * KBA));
            cp16(sbm + (j << 11), bs + j * (size_t)(16 * KBB));
        }
    };

    // warp/lane geometry: warp tile 64(M) x 64(N), warp grid 2x2
    const int wm = (w & 1) << 6;
    const int wn = (w >> 1) << 6;
    const uint32_t lx = (l & 7) << 4;
    const int arow = ((l >> 3) & 1) * 8 + (l & 7);
    const uint32_t ahb = (l >> 4) & 1;
    const int brow = ((l >> 4) & 1) * 8 + (l & 7);
    const uint32_t bhb = (l >> 3) & 1;

    float acc[128];
    #pragma unroll
    for (int i = 0; i < 128; i++) acc[i] = 0.f;

    uint32_t af[2][4][4], bf[2][4][4];

    load_chunk(0, 0);
    load_chunk(1, 1);

    #pragma unroll 1
    for (int c = 0; c < NCH; c++) {
        if (c < NCH - 2) cpwait<1>(); else cpwait<0>();
        __syncthreads();

        const uint32_t stA = sb + (c % 3) * STAGE_BYTES;
        const uint32_t stB = stA + 16384;
        const bool pf = (c + 2 < NCH);
        const int ps = (c + 2) % 3;

        auto load_frags = [&](int ks, int pb) {
            const uint32_t koffA = (((uint32_t)ks << 5) | (ahb << 4)) ^ lx;
            const uint32_t koffB = (((uint32_t)ks << 5) | (bhb << 4)) ^ lx;
            #pragma unroll
            for (int mt = 0; mt < 4; mt++)
                ldmx4(af[pb][mt], stA + ((uint32_t)(wm + mt * 16 + arow) << 7) + koffA);
            #pragma unroll
            for (int j = 0; j < 4; j++)
                ldmx4(bf[pb][j], stB + ((uint32_t)(wn + j * 16 + brow) << 7) + koffB);
        };

        load_frags(0, 0);
        #pragma unroll
        for (int ks = 0; ks < 4; ks++) {
            const int cur = ks & 1;
            if (pf) load_quarter(c + 2, ps, ks);          // spread producer issues
            if (ks < 3) load_frags(ks + 1, cur ^ 1);
            #pragma unroll
            for (int mt = 0; mt < 4; mt++)
                #pragma unroll
                for (int nt = 0; nt < 8; nt++)
                    mma16816(&acc[(mt * 8 + nt) * 4], af[cur][mt],
                             bf[cur][nt >> 1][(nt & 1) * 2], bf[cur][nt >> 1][(nt & 1) * 2 + 1]);
        }
        if (pf) cpcommit();
    }
    __syncthreads();   // retire last-stage reads before smem reuse

    // ------------- epilogue -------------
    const int cl = (l & 3) << 1;

    if (MODE == 0 && n0 >= 1024) {
        // KV tile: warp's 64 cols = [32 K-ch | 32 matching V-ch]; pair nt <-> nt+4
        const int hbase = ((n0 - 1024) >> 6) * 32;
        const int hw = hbase + (wn >> 1);
        const int bn = (int)(m0 / SEQ);
        float bk8[8], bv8[8];
        #pragma unroll
        for (int e = 0; e < 8; e++) {
            int hl = (e >> 1) * 8 + cl + (e & 1);
            bk8[e] = __ldg(&b1p[hw + hl]);
            bv8[e] = __ldg(&b2p[hw + hl]);
        }
        float pkv[8], pks[8];
        #pragma unroll
        for (int i = 0; i < 8; i++) { pkv[i] = 0.f; pks[i] = 0.f; }
        #pragma unroll
        for (int mt = 0; mt < 4; mt++)
            #pragma unroll
            for (int nt = 0; nt < 4; nt++)
                #pragma unroll
                for (int i = 0; i < 4; i++) {
                    int e = nt * 2 + (i & 1);
                    float kf = elu1(acc[(mt * 8 + nt) * 4 + i] + bk8[e]);
                    float vv = acc[(mt * 8 + nt + 4) * 4 + i] + bv8[e];
                    pkv[e] += kf * vv;
                    pks[e] += kf;
                }
        #pragma unroll
        for (int off = 16; off >= 4; off >>= 1)
            #pragma unroll
            for (int e = 0; e < 8; e++) {
                pkv[e] += __shfl_down_sync(0xffffffffu, pkv[e], off);
                pks[e] += __shfl_down_sync(0xffffffffu, pks[e], off);
            }
        float* redkv = (float*)smv;          // [4 warps][32]
        float* redks = redkv + 4 * 32;
        if (l < 4) {
            #pragma unroll
            for (int e = 0; e < 8; e++) {
                int hl = (e >> 1) * 8 + l * 2 + (e & 1);
                redkv[w * 32 + hl] = pkv[e];
                redks[w * 32 + hl] = pks[e];
            }
        }
        __syncthreads();
        {
            int cc = tid & 63;
            int w0 = (cc >> 5) * 2;          // warps {0,1} cols 0-63; {2,3} cols 64-127
            float* src = (tid < 64) ? redkv : redks;
            float s = src[w0 * 32 + (cc & 31)] + src[(w0 + 1) * 32 + (cc & 31)];
            float* dst = (tid < 64) ? &g_KV[bn * H + hbase + cc]
                                    : &g_Ksum[bn * H + hbase + cc];
            atomicAdd(dst, s);
        }
    } else {
        // Q tile (MODE 0, elu1 -> g_Qf fp16) or out tile (MODE 1, gelu -> fp32)
        float* ep = (float*)smv;             // [128][132]
        float bb[16];
        #pragma unroll
        for (int nt = 0; nt < 8; nt++) {
            bb[2 * nt]     = __ldg(&b0p[n0 + wn + nt * 8 + cl]);
            bb[2 * nt + 1] = __ldg(&b0p[n0 + wn + nt * 8 + cl + 1]);
        }
        #pragma unroll
        for (int mt = 0; mt < 4; mt++)
            #pragma unroll
            for (int nt = 0; nt < 8; nt++) {
                int c0 = wn + nt * 8 + cl;
                int r0 = wm + mt * 16 + (l >> 2);
                float v0 = acc[(mt * 8 + nt) * 4 + 0] + bb[2 * nt];
                float v1 = acc[(mt * 8 + nt) * 4 + 1] + bb[2 * nt + 1];
                float v2 = acc[(mt * 8 + nt) * 4 + 2] + bb[2 * nt];
                float v3 = acc[(mt * 8 + nt) * 4 + 3] + bb[2 * nt + 1];
                if (MODE == 0) { v0 = elu1(v0); v1 = elu1(v1); v2 = elu1(v2); v3 = elu1(v3); }
                else           { v0 = gelu(v0); v1 = gelu(v1); v2 = gelu(v2); v3 = gelu(v3); }
                ep[r0 * 132 + c0] = v0;        ep[r0 * 132 + c0 + 1] = v1;
                ep[(r0 + 8) * 132 + c0] = v2;  ep[(r0 + 8) * 132 + c0 + 1] = v3;
            }
        __syncthreads();
        if (MODE == 0) {
            #pragma unroll 8
            for (int i = 0; i < 128; i++) {
                int idx = i * 128 + tid;
                int rr = idx >> 7, cc = idx & 127;
                g_Qf[(m0 + rr) * H + n0 + cc] = __float2half(ep[rr * 132 + cc]);
            }
        } else {
            #pragma unroll 8
            for (int i = 0; i < 128; i++) {
                int idx = i * 128 + tid;
                int rr = idx >> 7, cc = idx & 127;
                outp[(m0 + rr) * H + n0 + cc] = ep[rr * 132 + cc];
            }
        }
    }
}

// ---------------- launch --------------------------------------------------
extern "C" void kernel_launch(void* const* d_in, const int* in_sizes, int n_in,
                              void* d_out, int out_size) {
    const float* x  = (const float*)d_in[0];
    const float* wq = (const float*)d_in[1];
    const float* bq = (const float*)d_in[2];
    const float* wk = (const float*)d_in[3];
    const float* bk = (const float*)d_in[4];
    const float* wv = (const float*)d_in[5];
    const float* bv = (const float*)d_in[6];
    const float* wo = (const float*)d_in[7];
    const float* bo = (const float*)d_in[8];
    float* out = (float*)d_out;

    cudaFuncSetAttribute(gemm_kernel<0>, cudaFuncAttributeMaxDynamicSharedMemorySize, SMEM_TOTAL);
    cudaFuncSetAttribute(gemm_kernel<1>, cudaFuncAttributeMaxDynamicSharedMemorySize, SMEM_TOTAL);

    conv_x_kernel<<<M_TOTAL * H / (256 * 8), 256>>>(x);
    conv_w_kernel<<<dim3(256, 4), 256>>>(wq, wk, wv, wo);

    gemm_kernel<0><<<dim3(24, M_TOTAL / 128), 128, SMEM_TOTAL>>>(bq, bk, bv, nullptr);
    vprime_kernel<<<M_TOTAL / 8, 256>>>();
    gemm_kernel<1><<<dim3(8, M_TOTAL / 128), 128, SMEM_TOTAL>>>(bo, nullptr, nullptr, out);
}

// round 16
// speedup vs baseline: 1.0813x; 1.0813x over previous
#include <cuda_runtime.h>
#include <cuda_fp16.h>
#include <cstdint>
#include <math.h>

#define M_TOTAL 32768
#define SEQ     8192
#define H       1024
#define NB      4
#define KBA     2048                 // bytes per A row (1024 fp16)
#define KBB     2048                 // bytes per B row (1024 fp16)
#define NCH     16                   // 16 K-chunks of 64 fp16 (128B)
#define STAGE_BYTES 32768            // 16KB A + 16KB B
#define SMEM_TOTAL (3*STAGE_BYTES)   // 96KB

// ---------------- scratch -----------------------------------------------
__device__ __half g_Ax[(size_t)M_TOTAL * H];     // x, fp16
__device__ __half g_Vp[(size_t)M_TOTAL * H];     // V', fp16
__device__ __half g_Qf[(size_t)M_TOTAL * H];     // elu(q)+1, fp16
__device__ __half g_Bqkv[(size_t)3072 * H];      // [Q rows | K/V interleaved rows]
__device__ __half g_Bo [(size_t)1024 * H];       // out weights
__device__ float  g_KV[NB * H];
__device__ float  g_Ksum[NB * H];

// ---------------- helpers ------------------------------------------------
__device__ __forceinline__ uint32_t smem_u32(const void* p) {
    uint32_t a;
    asm("{ .reg .u64 t; cvta.to.shared.u64 t, %1; cvt.u32.u64 %0, t; }" : "=r"(a) : "l"(p));
    return a;
}
__device__ __forceinline__ void cp16(uint32_t dst, const void* src) {
    asm volatile("cp.async.cg.shared.global [%0], [%1], 16;" :: "r"(dst), "l"(src));
}
__device__ __forceinline__ void cpcommit() {
    asm volatile("cp.async.commit_group;" ::: "memory");
}
template <int N> __device__ __forceinline__ void cpwait() {
    asm volatile("cp.async.wait_group %0;" :: "n"(N) : "memory");
}
__device__ __forceinline__ void ldmx4(uint32_t* r, uint32_t addr) {
    asm volatile("ldmatrix.sync.aligned.m8n8.x4.shared.b16 {%0,%1,%2,%3}, [%4];"
                 : "=r"(r[0]), "=r"(r[1]), "=r"(r[2]), "=r"(r[3]) : "r"(addr));
}
__device__ __forceinline__ void mma16816(float* d, const uint32_t* a, uint32_t b0, uint32_t b1) {
    asm volatile(
        "mma.sync.aligned.m16n8k16.row.col.f32.f16.f16.f32 "
        "{%0,%1,%2,%3}, {%4,%5,%6,%7}, {%8,%9}, {%0,%1,%2,%3};"
        : "+f"(d[0]), "+f"(d[1]), "+f"(d[2]), "+f"(d[3])
        : "r"(a[0]), "r"(a[1]), "r"(a[2]), "r"(a[3]), "r"(b0), "r"(b1));
}
__device__ __forceinline__ float elu1(float x) { return x > 0.f ? x + 1.f : __expf(x); }
__device__ __forceinline__ float fast_tanh(float x) {
    float y;
    asm("tanh.approx.f32 %0, %1;" : "=f"(y) : "f"(x));
    return y;
}
__device__ __forceinline__ float gelu(float v) {
    float t = 0.7978845608028654f * (v + 0.044715f * v * v * v);
    return 0.5f * v * (1.0f + fast_tanh(t));
}

// ---------------- small kernels ------------------------------------------
// x fp32 -> fp16, 8 elems/thread (+ first 16 blocks zero reduction buffers)
__global__ __launch_bounds__(256) void conv_x_kernel(const float* __restrict__ x) {
    if (blockIdx.x < 16) {
        int i = blockIdx.x * 256 + threadIdx.x;
        g_KV[i] = 0.f;
        g_Ksum[i] = 0.f;
    }
    size_t idx = (size_t)blockIdx.x * 256 + threadIdx.x;
    size_t e = idx << 3;
    float4 a = __ldcs((const float4*)&x[e]);        // x read exactly once
    float4 b = __ldcs((const float4*)&x[e + 4]);
    __half2 o[4];
    o[0] = {__float2half(a.x), __float2half(a.y)};
    o[1] = {__float2half(a.z), __float2half(a.w)};
    o[2] = {__float2half(b.x), __float2half(b.y)};
    o[3] = {__float2half(b.z), __float2half(b.w)};
    *(uint4*)&g_Ax[e] = *(uint4*)o;
}

// weights -> fp16 rows via tiled 64x64 smem transpose.
// B layout: rows 0-1023 = Q; rows 1024-3071 = K/V interleaved 64-blocks
// [32 K-ch | 32 matching V-ch]. Separate g_Bo for output weights.
__global__ __launch_bounds__(256) void conv_w_kernel(
    const float* __restrict__ wq, const float* __restrict__ wk,
    const float* __restrict__ wv, const float* __restrict__ wo) {
    __shared__ float s[64][65];
    const int tid = threadIdx.x;
    const int which = blockIdx.y;
    const int k0 = (blockIdx.x >> 4) * 64;
    const int h0 = (blockIdx.x & 15) * 64;
    const float* w = (which == 0) ? wq : (which == 1) ? wk : (which == 2) ? wv : wo;

    #pragma unroll
    for (int pass = 0; pass < 4; pass++) {
        int r = (tid >> 4) + pass * 16;
        int c4 = (tid & 15) << 2;
        float4 v = *(const float4*)&w[(size_t)(k0 + r) * H + h0 + c4];
        s[r][c4 + 0] = v.x; s[r][c4 + 1] = v.y;
        s[r][c4 + 2] = v.z; s[r][c4 + 3] = v.w;
    }
    __syncthreads();

    #pragma unroll
    for (int pass = 0; pass < 2; pass++) {
        int idx = pass * 256 + tid;
        int hh = idx >> 3;
        int seg = idx & 7;
        int h = h0 + hh;
        __half* row;
        if (which == 0)      row = &g_Bqkv[(size_t)h * H];
        else if (which == 1) row = &g_Bqkv[(size_t)(1024 + (h >> 5) * 64 + (h & 31)) * H];
        else if (which == 2) row = &g_Bqkv[(size_t)(1024 + (h >> 5) * 64 + 32 + (h & 31)) * H];
        else                 row = &g_Bo[(size_t)h * H];
        int kk = seg * 8;
        __half2 h4[4];
        #pragma unroll
        for (int i = 0; i < 4; i++)
            h4[i] = {__float2half(s[kk + 2 * i][hh]), __float2half(s[kk + 2 * i + 1][hh])};
        *(uint4*)&row[k0 + kk] = *(uint4*)h4;
    }
}

// V' = Qf*KV / (Qf*Ksum + 1e-6) -> fp16.
// Block = 32 rows of one batch; KV/Ksum cached in smem once per block.
__global__ __launch_bounds__(256) void vprime_kernel() {
    __shared__ float skv[H];
    __shared__ float sks[H];
    const int tid = threadIdx.x;
    const int m0 = blockIdx.x * 32;
    const int bn = m0 >> 13;                 // m0 / SEQ
    #pragma unroll
    for (int i = 0; i < 4; i++) {
        int h = i * 256 + tid;
        skv[h] = g_KV[bn * H + h];
        sks[h] = g_Ksum[bn * H + h];
    }
    __syncthreads();

    const size_t base = (size_t)m0 * H;
    #pragma unroll 4
    for (int it = 0; it < 16; it++) {
        size_t e = base + (size_t)it * 2048 + (size_t)tid * 8;
        int h = (int)(e & 1023);
        uint4 qr = *(const uint4*)&g_Qf[e];
        const __half* qh = (const __half*)&qr;
        float4 kv0 = *(const float4*)&skv[h];
        float4 kv1 = *(const float4*)&skv[h + 4];
        float4 ks0 = *(const float4*)&sks[h];
        float4 ks1 = *(const float4*)&sks[h + 4];
        float kva[8] = {kv0.x, kv0.y, kv0.z, kv0.w, kv1.x, kv1.y, kv1.z, kv1.w};
        float ksa[8] = {ks0.x, ks0.y, ks0.z, ks0.w, ks1.x, ks1.y, ks1.z, ks1.w};
        __half o[8];
        #pragma unroll
        for (int i = 0; i < 8; i++) {
            float q = __half2float(qh[i]);
            o[i] = __float2half(__fdividef(q * kva[i], fmaf(q, ksa[i], 1e-6f)));
        }
        *(uint4*)&g_Vp[e] = *(uint4*)o;
    }
}

// ---------------- HMMA GEMM ----------------------------------------------
// CTA tile 128x128, 128 threads (4 warps), warp tile 64x64, 3-stage pipe,
// 2 CTA/SM. Producer cp.async issues spread across the 4 ks iterations.
// MODE 0: fused QKV-GEMM (N=3072). n0<1024: Q tile -> elu1 -> g_Qf.
//         n0>=1024: KV tile -> per-channel reduction.
// MODE 1: out-GEMM (N=1024) -> bias+gelu -> out.
template <int MODE>
__global__ __launch_bounds__(128, 2) void gemm_kernel(
    const float* __restrict__ b0p,
    const float* __restrict__ b1p,
    const float* __restrict__ b2p,
    float* __restrict__ outp)
{
    extern __shared__ __align__(1024) char smv[];
    const uint32_t sb = smem_u32(smv);
    const int tid = threadIdx.x;
    const int w = tid >> 5, l = tid & 31;

    const size_t m0 = (size_t)blockIdx.y * 128;
    const int n0 = blockIdx.x * 128;

    const __half* A = (MODE == 1) ? g_Vp : g_Ax;
    const __half* B = (MODE == 1) ? g_Bo : g_Bqkv;

    // cp.async: 128 threads cover 128 rows x 128B for A and B each
    const char* Asrc = (const char*)A + (m0 + (tid >> 3)) * (size_t)KBA + ((tid & 7) << 4);
    const char* Bsrc = (const char*)B + ((size_t)(n0 + (tid >> 3))) * KBB + ((tid & 7) << 4);
    const uint32_t dst0 = ((tid >> 3) << 7) + ((((tid & 7) << 4)) ^ ((((tid >> 3) & 7)) << 4));

    auto load_chunk = [&](int ch, int s) {
        uint32_t sa = sb + s * STAGE_BYTES + dst0;
        uint32_t sbm = sa + 16384;
        const char* as = Asrc + (size_t)ch * 128;
        const char* bs = Bsrc + (size_t)ch * 128;
        #pragma unroll
        for (int j = 0; j < 8; j++) cp16(sa + (j << 11), as + j * (size_t)(16 * KBA));
        #pragma unroll
        for (int j = 0; j < 8; j++) cp16(sbm + (j << 11), bs + j * (size_t)(16 * KBB));
        cpcommit();
    };

    // quarter of a chunk load (2 A row-groups + 2 B row-groups per thread)
    auto load_quarter = [&](int ch, int s, int q) {
        uint32_t sa = sb + s * STAGE_BYTES + dst0;
        uint32_t sbm = sa + 16384;
        const char* as = Asrc + (size_t)ch * 128;
        const char* bs = Bsrc + (size_t)ch * 128;
        #pragma unroll
        for (int j = 2 * q; j < 2 * q + 2; j++) {
            cp16(sa + (j << 11), as + j * (size_t)(16 * KBA));
            cp16(sbm + (j << 11), bs + j * (size_t)(16 * KBB));
        }
    };

    // warp/lane geometry: warp tile 64(M) x 64(N), warp grid 2x2
    const int wm = (w & 1) << 6;
    const int wn = (w >> 1) << 6;
    const uint32_t lx = (l & 7) << 4;
    const int arow = ((l >> 3) & 1) * 8 + (l & 7);
    const uint32_t ahb = (l >> 4) & 1;
    const int brow = ((l >> 4) & 1) * 8 + (l & 7);
    const uint32_t bhb = (l >> 3) & 1;

    float acc[128];
    #pragma unroll
    for (int i = 0; i < 128; i++) acc[i] = 0.f;

    uint32_t af[2][4][4], bf[2][4][4];

    load_chunk(0, 0);
    load_chunk(1, 1);

    #pragma unroll 1
    for (int c = 0; c < NCH; c++) {
        if (c < NCH - 2) cpwait<1>(); else cpwait<0>();
        __syncthreads();

        const uint32_t stA = sb + (c % 3) * STAGE_BYTES;
        const uint32_t stB = stA + 16384;
        const bool pf = (c + 2 < NCH);
        const int ps = (c + 2) % 3;

        auto load_frags = [&](int ks, int pb) {
            const uint32_t koffA = (((uint32_t)ks << 5) | (ahb << 4)) ^ lx;
            const uint32_t koffB = (((uint32_t)ks << 5) | (bhb << 4)) ^ lx;
            #pragma unroll
            for (int mt = 0; mt < 4; mt++)
                ldmx4(af[pb][mt], stA + ((uint32_t)(wm + mt * 16 + arow) << 7) + koffA);
            #pragma unroll
            for (int j = 0; j < 4; j++)
                ldmx4(bf[pb][j], stB + ((uint32_t)(wn + j * 16 + brow) << 7) + koffB);
        };

        load_frags(0, 0);
        #pragma unroll
        for (int ks = 0; ks < 4; ks++) {
            const int cur = ks & 1;
            if (pf) load_quarter(c + 2, ps, ks);          // spread producer issues
            if (ks < 3) load_frags(ks + 1, cur ^ 1);
            #pragma unroll
            for (int mt = 0; mt < 4; mt++)
                #pragma unroll
                for (int nt = 0; nt < 8; nt++)
                    mma16816(&acc[(mt * 8 + nt) * 4], af[cur][mt],
                             bf[cur][nt >> 1][(nt & 1) * 2], bf[cur][nt >> 1][(nt & 1) * 2 + 1]);
        }
        if (pf) cpcommit();
    }
    __syncthreads();   // retire last-stage reads before smem reuse

    // ------------- epilogue -------------
    const int cl = (l & 3) << 1;

    if (MODE == 0 && n0 >= 1024) {
        // KV tile: warp's 64 cols = [32 K-ch | 32 matching V-ch]; pair nt <-> nt+4
        const int hbase = ((n0 - 1024) >> 6) * 32;
        const int hw = hbase + (wn >> 1);
        const int bn = (int)(m0 / SEQ);
        float bk8[8], bv8[8];
        #pragma unroll
        for (int e = 0; e < 8; e++) {
            int hl = (e >> 1) * 8 + cl + (e & 1);
            bk8[e] = __ldg(&b1p[hw + hl]);
            bv8[e] = __ldg(&b2p[hw + hl]);
        }
        float pkv[8], pks[8];
        #pragma unroll
        for (int i = 0; i < 8; i++) { pkv[i] = 0.f; pks[i] = 0.f; }
        #pragma unroll
        for (int mt = 0; mt < 4; mt++)
            #pragma unroll
            for (int nt = 0; nt < 4; nt++)
                #pragma unroll
                for (int i = 0; i < 4; i++) {
                    int e = nt * 2 + (i & 1);
                    float kf = elu1(acc[(mt * 8 + nt) * 4 + i] + bk8[e]);
                    float vv = acc[(mt * 8 + nt + 4) * 4 + i] + bv8[e];
                    pkv[e] += kf * vv;
                    pks[e] += kf;
                }
        #pragma unroll
        for (int off = 16; off >= 4; off >>= 1)
            #pragma unroll
            for (int e = 0; e < 8; e++) {
                pkv[e] += __shfl_down_sync(0xffffffffu, pkv[e], off);
                pks[e] += __shfl_down_sync(0xffffffffu, pks[e], off);
            }
        float* redkv = (float*)smv;          // [4 warps][32]
        float* redks = redkv + 4 * 32;
        if (l < 4) {
            #pragma unroll
            for (int e = 0; e < 8; e++) {
                int hl = (e >> 1) * 8 + l * 2 + (e & 1);
                redkv[w * 32 + hl] = pkv[e];
                redks[w * 32 + hl] = pks[e];
            }
        }
        __syncthreads();
        {
            int cc = tid & 63;
            int w0 = (cc >> 5) * 2;          // warps {0,1} cols 0-63; {2,3} cols 64-127
            float* src = (tid < 64) ? redkv : redks;
            float s = src[w0 * 32 + (cc & 31)] + src[(w0 + 1) * 32 + (cc & 31)];
            float* dst = (tid < 64) ? &g_KV[bn * H + hbase + cc]
                                    : &g_Ksum[bn * H + hbase + cc];
            atomicAdd(dst, s);
        }
    } else {
        // Q tile (MODE 0, elu1 -> g_Qf fp16) or out tile (MODE 1, gelu -> fp32)
        float* ep = (float*)smv;             // [128][132]
        float bb[16];
        #pragma unroll
        for (int nt = 0; nt < 8; nt++) {
            bb[2 * nt]     = __ldg(&b0p[n0 + wn + nt * 8 + cl]);
            bb[2 * nt + 1] = __ldg(&b0p[n0 + wn + nt * 8 + cl + 1]);
        }
        #pragma unroll
        for (int mt = 0; mt < 4; mt++)
            #pragma unroll
            for (int nt = 0; nt < 8; nt++) {
                int c0 = wn + nt * 8 + cl;
                int r0 = wm + mt * 16 + (l >> 2);
                float v0 = acc[(mt * 8 + nt) * 4 + 0] + bb[2 * nt];
                float v1 = acc[(mt * 8 + nt) * 4 + 1] + bb[2 * nt + 1];
                float v2 = acc[(mt * 8 + nt) * 4 + 2] + bb[2 * nt];
                float v3 = acc[(mt * 8 + nt) * 4 + 3] + bb[2 * nt + 1];
                if (MODE == 0) { v0 = elu1(v0); v1 = elu1(v1); v2 = elu1(v2); v3 = elu1(v3); }
                else           { v0 = gelu(v0); v1 = gelu(v1); v2 = gelu(v2); v3 = gelu(v3); }
                ep[r0 * 132 + c0] = v0;        ep[r0 * 132 + c0 + 1] = v1;
                ep[(r0 + 8) * 132 + c0] = v2;  ep[(r0 + 8) * 132 + c0 + 1] = v3;
            }
        __syncthreads();
        if (MODE == 0) {
            #pragma unroll 8
            for (int i = 0; i < 128; i++) {
                int idx = i * 128 + tid;
                int rr = idx >> 7, cc = idx & 127;
                g_Qf[(m0 + rr) * H + n0 + cc] = __float2half(ep[rr * 132 + cc]);
            }
        } else {
            #pragma unroll 8
            for (int i = 0; i < 128; i++) {
                int idx = i * 128 + tid;
                int rr = idx >> 7, cc = idx & 127;
                __stcs(&outp[(m0 + rr) * H + n0 + cc], ep[rr * 132 + cc]);   // out never re-read
            }
        }
    }
}

// ---------------- launch --------------------------------------------------
extern "C" void kernel_launch(void* const* d_in, const int* in_sizes, int n_in,
                              void* d_out, int out_size) {
    const float* x  = (const float*)d_in[0];
    const float* wq = (const float*)d_in[1];
    const float* bq = (const float*)d_in[2];
    const float* wk = (const float*)d_in[3];
    const float* bk = (const float*)d_in[4];
    const float* wv = (const float*)d_in[5];
    const float* bv = (const float*)d_in[6];
    const float* wo = (const float*)d_in[7];
    const float* bo = (const float*)d_in[8];
    float* out = (float*)d_out;

    cudaFuncSetAttribute(gemm_kernel<0>, cudaFuncAttributeMaxDynamicSharedMemorySize, SMEM_TOTAL);
    cudaFuncSetAttribute(gemm_kernel<1>, cudaFuncAttributeMaxDynamicSharedMemorySize, SMEM_TOTAL);

    conv_x_kernel<<<M_TOTAL * H / (256 * 8), 256>>>(x);
    conv_w_kernel<<<dim3(256, 4), 256>>>(wq, wk, wv, wo);

    gemm_kernel<0><<<dim3(24, M_TOTAL / 128), 128, SMEM_TOTAL>>>(bq, bk, bv, nullptr);
    vprime_kernel<<<M_TOTAL / 32, 256>>>();
    gemm_kernel<1><<<dim3(8, M_TOTAL / 128), 128, SMEM_TOTAL>>>(bo, nullptr, nullptr, out);
}

// round 17
// speedup vs baseline: 1.1005x; 1.0178x over previous
#include <cuda_runtime.h>
#include <cuda_fp16.h>
#include <cstdint>
#include <math.h>

#define M_TOTAL 32768
#define SEQ     8192
#define H       1024
#define NB      4
#define KBA     2048                 // bytes per A row (1024 fp16)
#define KBB     2048                 // bytes per B row (1024 fp16)
#define NCH     16                   // 16 K-chunks of 64 fp16 (128B)
#define STAGE_BYTES 32768            // 16KB A + 16KB B
#define SMEM_TOTAL (3*STAGE_BYTES)   // 96KB

// ---------------- scratch -----------------------------------------------
__device__ __half g_Ax[(size_t)M_TOTAL * H];     // x, fp16
__device__ __half g_Vp[(size_t)M_TOTAL * H];     // V', fp16
__device__ __half g_Qf[(size_t)M_TOTAL * H];     // elu(q)+1, fp16
__device__ __half g_Bqkv[(size_t)3072 * H];      // [Q rows | K/V interleaved rows]
__device__ __half g_Bo [(size_t)1024 * H];       // out weights
__device__ float  g_KV[NB * H];
__device__ float  g_Ksum[NB * H];

// ---------------- helpers ------------------------------------------------
__device__ __forceinline__ uint32_t smem_u32(const void* p) {
    uint32_t a;
    asm("{ .reg .u64 t; cvta.to.shared.u64 t, %1; cvt.u32.u64 %0, t; }" : "=r"(a) : "l"(p));
    return a;
}
__device__ __forceinline__ void cp16(uint32_t dst, const void* src) {
    asm volatile("cp.async.cg.shared.global [%0], [%1], 16;" :: "r"(dst), "l"(src));
}
__device__ __forceinline__ void cpcommit() {
    asm volatile("cp.async.commit_group;" ::: "memory");
}
template <int N> __device__ __forceinline__ void cpwait() {
    asm volatile("cp.async.wait_group %0;" :: "n"(N) : "memory");
}
__device__ __forceinline__ void ldmx4(uint32_t* r, uint32_t addr) {
    asm volatile("ldmatrix.sync.aligned.m8n8.x4.shared.b16 {%0,%1,%2,%3}, [%4];"
                 : "=r"(r[0]), "=r"(r[1]), "=r"(r[2]), "=r"(r[3]) : "r"(addr));
}
__device__ __forceinline__ void mma16816(float* d, const uint32_t* a, uint32_t b0, uint32_t b1) {
    asm volatile(
        "mma.sync.aligned.m16n8k16.row.col.f32.f16.f16.f32 "
        "{%0,%1,%2,%3}, {%4,%5,%6,%7}, {%8,%9}, {%0,%1,%2,%3};"
        : "+f"(d[0]), "+f"(d[1]), "+f"(d[2]), "+f"(d[3])
        : "r"(a[0]), "r"(a[1]), "r"(a[2]), "r"(a[3]), "r"(b0), "r"(b1));
}
__device__ __forceinline__ float elu1(float x) { return x > 0.f ? x + 1.f : __expf(x); }
__device__ __forceinline__ float fast_tanh(float x) {
    float y;
    asm("tanh.approx.f32 %0, %1;" : "=f"(y) : "f"(x));
    return y;
}
__device__ __forceinline__ float gelu(float v) {
    float t = 0.7978845608028654f * (v + 0.044715f * v * v * v);
    return 0.5f * v * (1.0f + fast_tanh(t));
}

// ---------------- fused conversion kernel ---------------------------------
// Blocks [0, NBX): x fp32 -> fp16 (first 16 also zero reduction buffers).
// Blocks [NBX, NBX+1024): weight transpose 64x64 tiles.
#define NBX (M_TOTAL * H / (256 * 8))     // 16384

__global__ __launch_bounds__(256) void conv_kernel(
    const float* __restrict__ x,
    const float* __restrict__ wq, const float* __restrict__ wk,
    const float* __restrict__ wv, const float* __restrict__ wo) {
    __shared__ float s[64][65];
    const int tid = threadIdx.x;

    if (blockIdx.x < NBX) {
        if (blockIdx.x < 16) {
            int i = blockIdx.x * 256 + tid;
            g_KV[i] = 0.f;
            g_Ksum[i] = 0.f;
        }
        size_t idx = (size_t)blockIdx.x * 256 + tid;
        size_t e = idx << 3;
        float4 a = __ldcs((const float4*)&x[e]);
        float4 b = __ldcs((const float4*)&x[e + 4]);
        __half2 o[4];
        o[0] = {__float2half(a.x), __float2half(a.y)};
        o[1] = {__float2half(a.z), __float2half(a.w)};
        o[2] = {__float2half(b.x), __float2half(b.y)};
        o[3] = {__float2half(b.z), __float2half(b.w)};
        *(uint4*)&g_Ax[e] = *(uint4*)o;
        return;
    }

    const int bx = blockIdx.x - NBX;      // 0..1023
    const int which = bx >> 8;            // 0..3
    const int tile = bx & 255;
    const int k0 = (tile >> 4) * 64;
    const int h0 = (tile & 15) * 64;
    const float* w = (which == 0) ? wq : (which == 1) ? wk : (which == 2) ? wv : wo;

    #pragma unroll
    for (int pass = 0; pass < 4; pass++) {
        int r = (tid >> 4) + pass * 16;
        int c4 = (tid & 15) << 2;
        float4 v = *(const float4*)&w[(size_t)(k0 + r) * H + h0 + c4];
        s[r][c4 + 0] = v.x; s[r][c4 + 1] = v.y;
        s[r][c4 + 2] = v.z; s[r][c4 + 3] = v.w;
    }
    __syncthreads();

    #pragma unroll
    for (int pass = 0; pass < 2; pass++) {
        int idx = pass * 256 + tid;
        int hh = idx >> 3;
        int seg = idx & 7;
        int h = h0 + hh;
        __half* row;
        if (which == 0)      row = &g_Bqkv[(size_t)h * H];
        else if (which == 1) row = &g_Bqkv[(size_t)(1024 + (h >> 5) * 64 + (h & 31)) * H];
        else if (which == 2) row = &g_Bqkv[(size_t)(1024 + (h >> 5) * 64 + 32 + (h & 31)) * H];
        else                 row = &g_Bo[(size_t)h * H];
        int kk = seg * 8;
        __half2 h4[4];
        #pragma unroll
        for (int i = 0; i < 4; i++)
            h4[i] = {__float2half(s[kk + 2 * i][hh]), __float2half(s[kk + 2 * i + 1][hh])};
        *(uint4*)&row[k0 + kk] = *(uint4*)h4;
    }
}

// V' = Qf*KV / (Qf*Ksum + 1e-6) -> fp16.
// Block = 32 rows of one batch; KV/Ksum cached in smem once per block.
__global__ __launch_bounds__(256) void vprime_kernel() {
    __shared__ float skv[H];
    __shared__ float sks[H];
    const int tid = threadIdx.x;
    const int m0 = blockIdx.x * 32;
    const int bn = m0 >> 13;                 // m0 / SEQ
    #pragma unroll
    for (int i = 0; i < 4; i++) {
        int h = i * 256 + tid;
        skv[h] = g_KV[bn * H + h];
        sks[h] = g_Ksum[bn * H + h];
    }
    __syncthreads();

    const size_t base = (size_t)m0 * H;
    #pragma unroll 4
    for (int it = 0; it < 16; it++) {
        size_t e = base + (size_t)it * 2048 + (size_t)tid * 8;
        int h = (int)(e & 1023);
        uint4 qr = *(const uint4*)&g_Qf[e];
        const __half* qh = (const __half*)&qr;
        float4 kv0 = *(const float4*)&skv[h];
        float4 kv1 = *(const float4*)&skv[h + 4];
        float4 ks0 = *(const float4*)&sks[h];
        float4 ks1 = *(const float4*)&sks[h + 4];
        float kva[8] = {kv0.x, kv0.y, kv0.z, kv0.w, kv1.x, kv1.y, kv1.z, kv1.w};
        float ksa[8] = {ks0.x, ks0.y, ks0.z, ks0.w, ks1.x, ks1.y, ks1.z, ks1.w};
        __half o[8];
        #pragma unroll
        for (int i = 0; i < 8; i++) {
            float q = __half2float(qh[i]);
            o[i] = __float2half(__fdividef(q * kva[i], fmaf(q, ksa[i], 1e-6f)));
        }
        *(uint4*)&g_Vp[e] = *(uint4*)o;
    }
}

// ---------------- HMMA GEMM ----------------------------------------------
// CTA tile 128x128, 128 threads (4 warps), warp tile 64x64, 3-stage pipe,
// 2 CTA/SM. Producer cp.async issues spread across the 4 ks iterations.
// MODE 0: fused QKV-GEMM (N=3072). n0<1024: Q tile -> elu1 -> g_Qf.
//         n0>=1024: KV tile -> per-channel reduction.
// MODE 1: out-GEMM (N=1024) -> bias+gelu -> out.
template <int MODE>
__global__ __launch_bounds__(128, 2) void gemm_kernel(
    const float* __restrict__ b0p,
    const float* __restrict__ b1p,
    const float* __restrict__ b2p,
    float* __restrict__ outp)
{
    extern __shared__ __align__(1024) char smv[];
    const uint32_t sb = smem_u32(smv);
    const int tid = threadIdx.x;
    const int w = tid >> 5, l = tid & 31;

    const size_t m0 = (size_t)blockIdx.y * 128;
    const int n0 = blockIdx.x * 128;

    const __half* A = (MODE == 1) ? g_Vp : g_Ax;
    const __half* B = (MODE == 1) ? g_Bo : g_Bqkv;

    // cp.async: 128 threads cover 128 rows x 128B for A and B each
    const char* Asrc = (const char*)A + (m0 + (tid >> 3)) * (size_t)KBA + ((tid & 7) << 4);
    const char* Bsrc = (const char*)B + ((size_t)(n0 + (tid >> 3))) * KBB + ((tid & 7) << 4);
    const uint32_t dst0 = ((tid >> 3) << 7) + ((((tid & 7) << 4)) ^ ((((tid >> 3) & 7)) << 4));

    auto load_chunk = [&](int ch, int s) {
        uint32_t sa = sb + s * STAGE_BYTES + dst0;
        uint32_t sbm = sa + 16384;
        const char* as = Asrc + (size_t)ch * 128;
        const char* bs = Bsrc + (size_t)ch * 128;
        #pragma unroll
        for (int j = 0; j < 8; j++) cp16(sa + (j << 11), as + j * (size_t)(16 * KBA));
        #pragma unroll
        for (int j = 0; j < 8; j++) cp16(sbm + (j << 11), bs + j * (size_t)(16 * KBB));
        cpcommit();
    };

    // quarter of a chunk load (2 A row-groups + 2 B row-groups per thread)
    auto load_quarter = [&](int ch, int s, int q) {
        uint32_t sa = sb + s * STAGE_BYTES + dst0;
        uint32_t sbm = sa + 16384;
        const char* as = Asrc + (size_t)ch * 128;
        const char* bs = Bsrc + (size_t)ch * 128;
        #pragma unroll
        for (int j = 2 * q; j < 2 * q + 2; j++) {
            cp16(sa + (j << 11), as + j * (size_t)(16 * KBA));
            cp16(sbm + (j << 11), bs + j * (size_t)(16 * KBB));
        }
    };

    // warp/lane geometry: warp tile 64(M) x 64(N), warp grid 2x2
    const int wm = (w & 1) << 6;
    const int wn = (w >> 1) << 6;
    const uint32_t lx = (l & 7) << 4;
    const int arow = ((l >> 3) & 1) * 8 + (l & 7);
    const uint32_t ahb = (l >> 4) & 1;
    const int brow = ((l >> 4) & 1) * 8 + (l & 7);
    const uint32_t bhb = (l >> 3) & 1;

    float acc[128];
    #pragma unroll
    for (int i = 0; i < 128; i++) acc[i] = 0.f;

    uint32_t af[2][4][4], bf[2][4][4];

    load_chunk(0, 0);
    load_chunk(1, 1);

    #pragma unroll 1
    for (int c = 0; c < NCH; c++) {
        if (c < NCH - 2) cpwait<1>(); else cpwait<0>();
        __syncthreads();

        const uint32_t stA = sb + (c % 3) * STAGE_BYTES;
        const uint32_t stB = stA + 16384;
        const bool pf = (c + 2 < NCH);
        const int ps = (c + 2) % 3;

        auto load_frags = [&](int ks, int pb) {
            const uint32_t koffA = (((uint32_t)ks << 5) | (ahb << 4)) ^ lx;
            const uint32_t koffB = (((uint32_t)ks << 5) | (bhb << 4)) ^ lx;
            #pragma unroll
            for (int mt = 0; mt < 4; mt++)
                ldmx4(af[pb][mt], stA + ((uint32_t)(wm + mt * 16 + arow) << 7) + koffA);
            #pragma unroll
            for (int j = 0; j < 4; j++)
                ldmx4(bf[pb][j], stB + ((uint32_t)(wn + j * 16 + brow) << 7) + koffB);
        };

        load_frags(0, 0);
        #pragma unroll
        for (int ks = 0; ks < 4; ks++) {
            const int cur = ks & 1;
            if (pf) load_quarter(c + 2, ps, ks);          // spread producer issues
            if (ks < 3) load_frags(ks + 1, cur ^ 1);
            #pragma unroll
            for (int mt = 0; mt < 4; mt++)
                #pragma unroll
                for (int nt = 0; nt < 8; nt++)
                    mma16816(&acc[(mt * 8 + nt) * 4], af[cur][mt],
                             bf[cur][nt >> 1][(nt & 1) * 2], bf[cur][nt >> 1][(nt & 1) * 2 + 1]);
        }
        if (pf) cpcommit();
    }
    __syncthreads();   // retire last-stage reads before smem reuse

    // ------------- epilogue -------------
    const int cl = (l & 3) << 1;

    if (MODE == 0 && n0 >= 1024) {
        // KV tile: warp's 64 cols = [32 K-ch | 32 matching V-ch]; pair nt <-> nt+4
        const int hbase = ((n0 - 1024) >> 6) * 32;
        const int hw = hbase + (wn >> 1);
        const int bn = (int)(m0 / SEQ);
        float bk8[8], bv8[8];
        #pragma unroll
        for (int e = 0; e < 8; e++) {
            int hl = (e >> 1) * 8 + cl + (e & 1);
            bk8[e] = __ldg(&b1p[hw + hl]);
            bv8[e] = __ldg(&b2p[hw + hl]);
        }
        float pkv[8], pks[8];
        #pragma unroll
        for (int i = 0; i < 8; i++) { pkv[i] = 0.f; pks[i] = 0.f; }
        #pragma unroll
        for (int mt = 0; mt < 4; mt++)
            #pragma unroll
            for (int nt = 0; nt < 4; nt++)
                #pragma unroll
                for (int i = 0; i < 4; i++) {
                    int e = nt * 2 + (i & 1);
                    float kf = elu1(acc[(mt * 8 + nt) * 4 + i] + bk8[e]);
                    float vv = acc[(mt * 8 + nt + 4) * 4 + i] + bv8[e];
                    pkv[e] += kf * vv;
                    pks[e] += kf;
                }
        #pragma unroll
        for (int off = 16; off >= 4; off >>= 1)
            #pragma unroll
            for (int e = 0; e < 8; e++) {
                pkv[e] += __shfl_down_sync(0xffffffffu, pkv[e], off);
                pks[e] += __shfl_down_sync(0xffffffffu, pks[e], off);
            }
        float* redkv = (float*)smv;          // [4 warps][32]
        float* redks = redkv + 4 * 32;
        if (l < 4) {
            #pragma unroll
            for (int e = 0; e < 8; e++) {
                int hl = (e >> 1) * 8 + l * 2 + (e & 1);
                redkv[w * 32 + hl] = pkv[e];
                redks[w * 32 + hl] = pks[e];
            }
        }
        __syncthreads();
        {
            int cc = tid & 63;
            int w0 = (cc >> 5) * 2;          // warps {0,1} cols 0-63; {2,3} cols 64-127
            float* src = (tid < 64) ? redkv : redks;
            float s = src[w0 * 32 + (cc & 31)] + src[(w0 + 1) * 32 + (cc & 31)];
            float* dst = (tid < 64) ? &g_KV[bn * H + hbase + cc]
                                    : &g_Ksum[bn * H + hbase + cc];
            atomicAdd(dst, s);
        }
    } else if (MODE == 0) {
        // Q tile: elu1 -> fp16 smem staging (pitch 136) -> 16B vector copy-out
        __half* eph = (__half*)smv;          // [128][136]
        float bb[16];
        #pragma unroll
        for (int nt = 0; nt < 8; nt++) {
            bb[2 * nt]     = __ldg(&b0p[n0 + wn + nt * 8 + cl]);
            bb[2 * nt + 1] = __ldg(&b0p[n0 + wn + nt * 8 + cl + 1]);
        }
        #pragma unroll
        for (int mt = 0; mt < 4; mt++)
            #pragma unroll
            for (int nt = 0; nt < 8; nt++) {
                int c0 = wn + nt * 8 + cl;
                int r0 = wm + mt * 16 + (l >> 2);
                float v0 = elu1(acc[(mt * 8 + nt) * 4 + 0] + bb[2 * nt]);
                float v1 = elu1(acc[(mt * 8 + nt) * 4 + 1] + bb[2 * nt + 1]);
                float v2 = elu1(acc[(mt * 8 + nt) * 4 + 2] + bb[2 * nt]);
                float v3 = elu1(acc[(mt * 8 + nt) * 4 + 3] + bb[2 * nt + 1]);
                *(__half2*)&eph[r0 * 136 + c0]       = __floats2half2_rn(v0, v1);
                *(__half2*)&eph[(r0 + 8) * 136 + c0] = __floats2half2_rn(v2, v3);
            }
        __syncthreads();
        #pragma unroll
        for (int i = 0; i < 16; i++) {
            int idx = i * 128 + tid;             // 0..2047
            int rr = idx >> 4;                   // 0..127
            int c8 = (idx & 15) << 3;            // 0..120
            uint4 v = *(uint4*)&eph[rr * 136 + c8];
            *(uint4*)&g_Qf[(m0 + rr) * H + n0 + c8] = v;
        }
    } else {
        // MODE 1: gelu -> fp32 smem staging -> float4 streaming copy-out
        float* ep = (float*)smv;             // [128][132]
        float bb[16];
        #pragma unroll
        for (int nt = 0; nt < 8; nt++) {
            bb[2 * nt]     = __ldg(&b0p[n0 + wn + nt * 8 + cl]);
            bb[2 * nt + 1] = __ldg(&b0p[n0 + wn + nt * 8 + cl + 1]);
        }
        #pragma unroll
        for (int mt = 0; mt < 4; mt++)
            #pragma unroll
            for (int nt = 0; nt < 8; nt++) {
                int c0 = wn + nt * 8 + cl;
                int r0 = wm + mt * 16 + (l >> 2);
                ep[r0 * 132 + c0]           = gelu(acc[(mt * 8 + nt) * 4 + 0] + bb[2 * nt]);
                ep[r0 * 132 + c0 + 1]       = gelu(acc[(mt * 8 + nt) * 4 + 1] + bb[2 * nt + 1]);
                ep[(r0 + 8) * 132 + c0]     = gelu(acc[(mt * 8 + nt) * 4 + 2] + bb[2 * nt]);
                ep[(r0 + 8) * 132 + c0 + 1] = gelu(acc[(mt * 8 + nt) * 4 + 3] + bb[2 * nt + 1]);
            }
        __syncthreads();
        #pragma unroll
        for (int i = 0; i < 32; i++) {
            int idx = i * 128 + tid;             // 0..4095
            int rr = idx >> 5;                   // 0..127
            int c4 = (idx & 31) << 2;            // 0..124
            float4 v = *(float4*)&ep[rr * 132 + c4];
            __stcs((float4*)&outp[(m0 + rr) * H + n0 + c4], v);
        }
    }
}

// ---------------- launch --------------------------------------------------
extern "C" void kernel_launch(void* const* d_in, const int* in_sizes, int n_in,
                              void* d_out, int out_size) {
    const float* x  = (const float*)d_in[0];
    const float* wq = (const float*)d_in[1];
    const float* bq = (const float*)d_in[2];
    const float* wk = (const float*)d_in[3];
    const float* bk = (const float*)d_in[4];
    const float* wv = (const float*)d_in[5];
    const float* bv = (const float*)d_in[6];
    const float* wo = (const float*)d_in[7];
    const float* bo = (const float*)d_in[8];
    float* out = (float*)d_out;

    cudaFuncSetAttribute(gemm_kernel<0>, cudaFuncAttributeMaxDynamicSharedMemorySize, SMEM_TOTAL);
    cudaFuncSetAttribute(gemm_kernel<1>, cudaFuncAttributeMaxDynamicSharedMemorySize, SMEM_TOTAL);

    conv_kernel<<<NBX + 1024, 256>>>(x, wq, wk, wv, wo);

    gemm_kernel<0><<<dim3(24, M_TOTAL / 128), 128, SMEM_TOTAL>>>(bq, bk, bv, nullptr);
    vprime_kernel<<<M_TOTAL / 32, 256>>>();
    gemm_kernel<1><<<dim3(8, M_TOTAL / 128), 128, SMEM_TOTAL>>>(bo, nullptr, nullptr, out);
}